// round 12
// baseline (speedup 1.0000x reference)
#include <cuda_runtime.h>

#define NB    50000
#define DIM   51
#define DD    2601
#define BATCH 8192

#define BMV_BLOCKS   8192                  // 4 warp-samples each
#define SMALL_BLOCKS 64                    // 128 samples each
#define BMVK_BLOCKS  (BMV_BLOCKS + SMALL_BLOCKS)
#define CHAIN_BLOCKS 8192                  // 1 sample each

#define PART_CHAIN 0
#define PART_BMV   8192
#define PART_SMALL (PART_BMV + 4 * BMV_BLOCKS)   // 40960
#define PART_TOTAL (PART_SMALL + SMALL_BLOCKS)   // 41024

__device__ float g_part[PART_TOTAL];

#define FULLMASK 0xffffffffu

// ---- packed f32x2 helpers (sm_100+) ---------------------------------------
__device__ __forceinline__ unsigned long long pack2(float lo, float hi) {
    unsigned long long r;
    asm("mov.b64 %0, {%1, %2};" : "=l"(r) : "f"(lo), "f"(hi));
    return r;
}
__device__ __forceinline__ void unpack2(unsigned long long v, float &lo, float &hi) {
    asm("mov.b64 {%0, %1}, %2;" : "=f"(lo), "=f"(hi) : "l"(v));
}
__device__ __forceinline__ void ffma2(unsigned long long &d,
                                      unsigned long long a, unsigned long long b) {
    asm("fma.rn.f32x2 %0, %1, %2, %3;" : "=l"(d) : "l"(a), "l"(b), "l"(d));
}

// Merge-reduce 4 values with 6 shfls; lane picks result by (bit16,bit8):
// (0,0)->p0 (1,0)->p1 (0,1)->p2 (1,1)->p3.
__device__ __forceinline__ float merge4(float p0, float p1, float p2, float p3,
                                        int lane)
{
    const bool b16 = (lane & 16) != 0;
    const bool b8  = (lane & 8)  != 0;
    float x1 = (b16 ? p1 : p0) + __shfl_xor_sync(FULLMASK, b16 ? p0 : p1, 16);
    float x2 = (b16 ? p3 : p2) + __shfl_xor_sync(FULLMASK, b16 ? p2 : p3, 16);
    float y  = (b8 ? x2 : x1)  + __shfl_xor_sync(FULLMASK, b8 ? x1 : x2, 8);
    y += __shfl_xor_sync(FULLMASK, y, 4);
    y += __shfl_xor_sync(FULLMASK, y, 2);
    y += __shfl_xor_sync(FULLMASK, y, 1);
    return y;
}

// ===========================================================================
// CHAIN v3b: register-tiled 64x64x51 GEMM, 1 sample / 128-thread block.
// Thread (tx,ty): tx=tid&7 -> rows [8tx,8tx+8), ty=tid>>3 -> cols [4ty,4ty+4).
// 8x4 tile = 16 b64 accumulators. CsT[k][i] (transposed C), Ds[k][j],
// stride LDW=52 floats. IMPORTANT: arrays are allocated with 52 k-rows
// (52*LDW floats) so the pad-thread tile reads (up to index 2663) stay
// inside each array — the R11 overrun past the smem window caused the trap.
// Pad values are garbage by design; epilogue guards skip them.
// E staged through smem (coalesced) reusing CsT after the k-loop.
// ===========================================================================
#define LDW 52
__global__ void __launch_bounds__(128) chain_kernel(
    const int* __restrict__ nfc, const float* __restrict__ rel)
{
    __shared__ __align__(16) float CsT[52 * LDW];   // 10816 B (padded)
    __shared__ __align__(16) float Ds [52 * LDW];   // 10816 B (padded)
    __shared__ float red[4];

    const int s   = blockIdx.x;
    const int tid = threadIdx.x;
    const int tx  = tid & 7;
    const int ty  = tid >> 3;
    const int i0 = nfc[3 * s], i1 = nfc[3 * s + 1], i2 = nfc[3 * s + 2];

    {
        const float* __restrict__ C  = rel + (long)i0 * DD;
        const float* __restrict__ Dm = rel + (long)i1 * DD;
        #pragma unroll 3
        for (int t = tid; t < DD; t += 128) {
            const int i = t / 51;
            const int k = t - i * 51;
            CsT[k * LDW + i] = C[t];
        }
        #pragma unroll 3
        for (int t = tid; t < DD; t += 128) {
            const int k = t / 51;
            const int j = t - k * 51;
            Ds[k * LDW + j] = Dm[t];
        }
    }
    __syncthreads();

    unsigned long long acc[8][2];
    #pragma unroll
    for (int r = 0; r < 8; r++) { acc[r][0] = 0ull; acc[r][1] = 0ull; }

    const float* __restrict__ cptr = CsT + 8 * tx;
    const float* __restrict__ dptr = Ds  + 4 * ty;

    #pragma unroll 3
    for (int k = 0; k < DIM; k++) {
        const float4 cA = *(const float4*)(cptr + k * LDW);
        const float4 cB = *(const float4*)(cptr + k * LDW + 4);
        const ulonglong2 dd = *(const ulonglong2*)(dptr + k * LDW);
        const float c[8] = {cA.x, cA.y, cA.z, cA.w, cB.x, cB.y, cB.z, cB.w};
        #pragma unroll
        for (int r = 0; r < 8; r++) {
            const unsigned long long cr2 = pack2(c[r], c[r]);
            ffma2(acc[r][0], cr2, dd.x);
            ffma2(acc[r][1], cr2, dd.y);
        }
    }
    __syncthreads();

    // stage E coalesced into CsT (linear layout, 2601 <= 2704 floats)
    {
        const float* __restrict__ E = rel + (long)i2 * DD;
        #pragma unroll 3
        for (int t = tid; t < DD; t += 128) CsT[t] = E[t];
    }
    __syncthreads();

    float local = 0.f;
    const int jb = 4 * ty;
    if (jb < DIM) {
        #pragma unroll
        for (int r = 0; r < 8; r++) {
            const int i = 8 * tx + r;
            if (i < DIM) {
                const float* __restrict__ Er = CsT + i * DIM + jb;
                float v0, v1, v2, v3;
                unpack2(acc[r][0], v0, v1);
                unpack2(acc[r][1], v2, v3);
                local += fabsf(Er[0] - v0);
                if (jb + 1 < DIM) local += fabsf(Er[1] - v1);
                if (jb + 2 < DIM) local += fabsf(Er[2] - v2);
                if (jb + 3 < DIM) local += fabsf(Er[3] - v3);
            }
        }
    }
    #pragma unroll
    for (int o = 16; o; o >>= 1)
        local += __shfl_xor_sync(FULLMASK, local, o);
    if ((tid & 31) == 0) red[tid >> 5] = local;
    __syncthreads();
    if (tid == 0)
        g_part[PART_CHAIN + s] =
            (red[0] + red[1] + red[2] + red[3]) * (1.0f / (float)DD);
}

// ===========================================================================
// BMV (warp/sample) + SMALL tail blocks. (unchanged: 69 us, 57% DRAM, occ 83%)
// ===========================================================================
__global__ void __launch_bounds__(128) bmv_kernel(
    const int* __restrict__ nf1,  const int* __restrict__ nf2,
    const int* __restrict__ nf3,  const int* __restrict__ nf4,
    const int* __restrict__ top,  const int* __restrict__ nf3n,
    const int* __restrict__ radius,
    const float* __restrict__ cls, const float* __restrict__ rel)
{
    const int g   = blockIdx.x;
    const int tid = threadIdx.x;

    if (g < BMV_BLOCKS) {
        const int wl   = tid >> 5;
        const int lane = tid & 31;
        const int w    = g * 4 + wl;
        const int mode = w >> 13;
        const int s    = w & (BATCH - 1);

        const int* __restrict__ idx =
            (mode == 0) ? nf1 : (mode == 1) ? nf3 : (mode == 2) ? nf4 : nf3n;
        int ic, ir, id_;
        if (mode == 2) { ir = idx[3 * s]; ic = idx[3 * s + 1]; id_ = idx[3 * s + 2]; }
        else           { ic = idx[3 * s]; ir = idx[3 * s + 1]; id_ = idx[3 * s + 2]; }

        const float* __restrict__ rm = rel + (long)ir * DD;
        const bool hi = (lane < DIM - 32);      // lanes 0..18

        float xa[4], xb[4], na[4], nb[4];
        #pragma unroll
        for (int u = 0; u < 4; u++) {
            const float* __restrict__ row = rm + u * DIM;
            xa[u] = row[lane];
            xb[u] = hi ? row[lane + 32] : 0.f;
        }
        #pragma unroll
        for (int u = 0; u < 4; u++) {
            const float* __restrict__ row = rm + (4 + u) * DIM;
            na[u] = row[lane];
            nb[u] = hi ? row[lane + 32] : 0.f;
        }
        const float* __restrict__ cp = cls + (long)ic  * DIM;
        const float* __restrict__ dp = cls + (long)id_ * DIM;
        const float c0 = cp[lane];
        const float d0 = dp[lane];
        const float c1 = hi ? cp[lane + 32] : 0.f;
        const float d1 = hi ? dp[lane + 32] : 0.f;
        const float* __restrict__ r50 = rm + 50 * DIM;
        const float r50a = r50[lane];
        const float r50b = hi ? r50[lane + 32] : 0.f;

        const float e0 = d0 - c0;
        const float e1 = d1 - c1;

        const float scp = c0 * c0 + ((lane < 18) ? c1 * c1 : 0.f);
        const float sdp = d0 * d0 + ((lane < 18) ? d1 * d1 : 0.f);
        float scv;
        {
            const bool b16 = (lane & 16) != 0;
            float v = (b16 ? sdp : scp) +
                      __shfl_xor_sync(FULLMASK, b16 ? scp : sdp, 16);
            v += __shfl_xor_sync(FULLMASK, v, 8);
            v += __shfl_xor_sync(FULLMASK, v, 4);
            v += __shfl_xor_sync(FULLMASK, v, 2);
            v += __shfl_xor_sync(FULLMASK, v, 1);
            scv = v;
        }
        const float sc_tot = __shfl_sync(FULLMASK, scv, 0);
        const float sd_tot = __shfl_sync(FULLMASK, scv, 16);
        const float c_last = __shfl_sync(FULLMASK, c1, 18);
        const float d_last = __shfl_sync(FULLMASK, d1, 18);

        float vsq = 0.f;
        #pragma unroll
        for (int gr = 0; gr < 13; gr++) {
            float p[4];
            float* A = ((gr & 1) == 0) ? xa : na;
            float* B = ((gr & 1) == 0) ? xb : nb;
            #pragma unroll
            for (int u = 0; u < 4; u++) {
                const bool valid = (4 * gr + u) < 50;
                p[u] = valid ? (A[u] * e0 + B[u] * e1) : 0.f;
            }
            if (gr + 2 < 13) {
                #pragma unroll
                for (int u = 0; u < 4; u++) {
                    const int r = (gr + 2) * 4 + u;
                    if (r < 50) {
                        const float* __restrict__ row = rm + r * DIM;
                        A[u] = row[lane];
                        B[u] = hi ? row[lane + 32] : 0.f;
                    }
                }
            }
            const float y = merge4(p[0], p[1], p[2], p[3], lane);
            vsq = fmaf(y, y, vsq);
        }
        #pragma unroll
        for (int o = 16; o; o >>= 1)
            vsq += __shfl_xor_sync(FULLMASK, vsq, o);
        const float euc = sqrtf(vsq * 0.125f);   // sum vsq = 8 * euc2

        float core;
        if (mode == 0) {
            const float pcp = r50a * c0 + r50b * c1;
            const float pdp = r50a * d0 + r50b * d1;
            const float yv = merge4(pcp, pdp, 0.f, 0.f, lane);
            const float pc = __shfl_sync(FULLMASK, yv, 0);
            const float pd = __shfl_sync(FULLMASK, yv, 16);
            core = fmaxf(euc + fmaxf(pc, 0.f) - fmaxf(pd, 0.f), 0.f);
        } else {
            const float rc = fmaxf(c_last, 0.f);
            const float rd = fmaxf(d_last, 0.f);
            if (mode == 1)      core = fmaxf(euc + rc - rd, 0.f);
            else if (mode == 2) core = fmaxf(euc - rc - rd, 0.f);
            else                core = rc + rd - euc;           // nf3_neg
        }
        if (lane == 0)
            g_part[PART_BMV + w] = core + fabsf(sqrtf(sc_tot) - 1.0f)
                                        + fabsf(sqrtf(sd_tot) - 1.0f);

    } else {
        // ------------------------- SMALL (nf2 + top - radius) -------------
        __shared__ float red[4];
        const int s = (g - BMV_BLOCKS) * 128 + tid;
        const float* __restrict__ c = cls + (long)nf2[3 * s]     * DIM;
        const float* __restrict__ d = cls + (long)nf2[3 * s + 1] * DIM;
        const float* __restrict__ e = cls + (long)nf2[3 * s + 2] * DIM;

        float s12 = 0.f, s13 = 0.f, s23 = 0.f, n1 = 0.f, n2 = 0.f, n3 = 0.f;
        #pragma unroll 5
        for (int k = 0; k < DIM - 1; k++) {
            const float x1 = c[k], x2 = d[k], x3 = e[k];
            const float d12 = x2 - x1, d13 = x3 - x1, d23 = x3 - x2;
            s12 = fmaf(d12, d12, s12);
            s13 = fmaf(d13, d13, s13);
            s23 = fmaf(d23, d23, s23);
            n1  = fmaf(x1, x1, n1);
            n2  = fmaf(x2, x2, n2);
            n3  = fmaf(x3, x3, n3);
        }
        const float rc = fmaxf(c[DIM - 1], 0.f);
        const float rd = fmaxf(d[DIM - 1], 0.f);
        const float re = fmaxf(e[DIM - 1], 0.f);
        float v = fmaxf(sqrtf(s12) - (rc + rd), 0.f)
                + fmaxf(sqrtf(s13) - rc, 0.f)
                + fmaxf(sqrtf(s23) - rd, 0.f)
                + fmaxf(fminf(rc, rd) - re, 0.f)
                + fabsf(sqrtf(n1) - 1.f)
                + fabsf(sqrtf(n2) - 1.f)
                + fabsf(sqrtf(n3) - 1.f);

        v += fabsf(fmaxf(cls[(long)top[s] * DIM + (DIM - 1)], 0.f) - 5.0f);
        v -= fminf(0.f, cls[(long)radius[s] * DIM + (DIM - 1)]);

        #pragma unroll
        for (int o = 16; o; o >>= 1)
            v += __shfl_xor_sync(FULLMASK, v, o);
        if ((tid & 31) == 0) red[tid >> 5] = v;
        __syncthreads();
        if (tid == 0)
            g_part[PART_SMALL + (g - BMV_BLOCKS)] =
                (red[0] + red[1]) + (red[2] + red[3]);
    }
}

// ---------------------------------------------------------------------------
__global__ void __launch_bounds__(1024) finish_kernel(float* __restrict__ out)
{
    float t = 0.f;
    for (int i = threadIdx.x; i < PART_TOTAL; i += 1024) t += g_part[i];
    #pragma unroll
    for (int o = 16; o; o >>= 1)
        t += __shfl_xor_sync(FULLMASK, t, o);
    __shared__ float ws[32];
    if ((threadIdx.x & 31) == 0) ws[threadIdx.x >> 5] = t;
    __syncthreads();
    if (threadIdx.x < 32) {
        float v = ws[threadIdx.x];
        #pragma unroll
        for (int o = 16; o; o >>= 1)
            v += __shfl_xor_sync(FULLMASK, v, o);
        if (threadIdx.x == 0) out[0] = v * (1.0f / (float)BATCH);
    }
}

// ---------------------------------------------------------------------------
// Side stream + events for chain||bmv overlap, created once at process start
// (host-side driver resources only; no device memory allocation).
// ---------------------------------------------------------------------------
static cudaStream_t g_s2 = 0;
static cudaEvent_t  g_evA = 0, g_evB = 0;
namespace {
struct StreamInit {
    StreamInit() {
        if (cudaStreamCreateWithFlags(&g_s2, cudaStreamNonBlocking) != cudaSuccess) {
            g_s2 = 0;
            return;
        }
        if (cudaEventCreateWithFlags(&g_evA, cudaEventDisableTiming) != cudaSuccess ||
            cudaEventCreateWithFlags(&g_evB, cudaEventDisableTiming) != cudaSuccess) {
            g_s2 = 0;
        }
    }
};
static StreamInit g_streamInit;
}

// ---------------------------------------------------------------------------
// Inputs: 0 nf1 1 nf2 2 nf3 3 nf4 4 top 5 nf3_neg 6 nf_inclusion(unused)
//         7 nf_chain 8 radius 9 cls_emb 10 rel_emb
// chain on the launch stream, bmv forked onto g_s2 (joined before finish).
// Kernel-launch order chain,bmv,finish -> profiled launch (#4) = chain.
// ---------------------------------------------------------------------------
extern "C" void kernel_launch(void* const* d_in, const int* in_sizes, int n_in,
                              void* d_out, int out_size)
{
    const int*   nf1    = (const int*)d_in[0];
    const int*   nf2    = (const int*)d_in[1];
    const int*   nf3    = (const int*)d_in[2];
    const int*   nf4    = (const int*)d_in[3];
    const int*   top    = (const int*)d_in[4];
    const int*   nf3n   = (const int*)d_in[5];
    const int*   nfc    = (const int*)d_in[7];
    const int*   radius = (const int*)d_in[8];
    const float* cls    = (const float*)d_in[9];
    const float* rel    = (const float*)d_in[10];
    float*       out    = (float*)d_out;

    if (g_s2) {
        cudaEventRecord(g_evA, 0);
        cudaStreamWaitEvent(g_s2, g_evA, 0);
        chain_kernel<<<CHAIN_BLOCKS, 128>>>(nfc, rel);
        bmv_kernel<<<BMVK_BLOCKS, 128, 0, g_s2>>>(nf1, nf2, nf3, nf4, top,
                                                  nf3n, radius, cls, rel);
        cudaEventRecord(g_evB, g_s2);
        cudaStreamWaitEvent(0, g_evB, 0);
        finish_kernel<<<1, 1024>>>(out);
    } else {
        chain_kernel<<<CHAIN_BLOCKS, 128>>>(nfc, rel);
        bmv_kernel<<<BMVK_BLOCKS, 128>>>(nf1, nf2, nf3, nf4, top, nf3n,
                                         radius, cls, rel);
        finish_kernel<<<1, 1024>>>(out);
    }
}

// round 17
// speedup vs baseline: 1.4254x; 1.4254x over previous
#include <cuda_runtime.h>
#include <cuda_bf16.h>

#define NB    50000
#define DIM   51
#define DD    2601
#define BATCH 8192

#define BMV_BLOCKS   8192                  // 4 warp-samples each
#define SMALL_BLOCKS 64                    // 128 samples each
#define BMVK_BLOCKS  (BMV_BLOCKS + SMALL_BLOCKS)
#define CHAIN_BLOCKS 8192                  // 1 sample each

#define PART_CHAIN 0
#define PART_BMV   8192
#define PART_SMALL (PART_BMV + 4 * BMV_BLOCKS)   // 40960
#define PART_TOTAL (PART_SMALL + SMALL_BLOCKS)   // 41024

__device__ float g_part[PART_TOTAL];

#define FULLMASK 0xffffffffu

// ---------------------------------------------------------------------------
// helpers
// ---------------------------------------------------------------------------
__device__ __forceinline__ unsigned smem_u32(const void* p) {
    unsigned a;
    asm("{ .reg .u64 t; cvta.to.shared.u64 t, %1; cvt.u32.u64 %0, t; }"
        : "=r"(a) : "l"(p));
    return a;
}
__device__ __forceinline__ void ldsm_x4(unsigned &r0, unsigned &r1,
                                        unsigned &r2, unsigned &r3,
                                        unsigned addr) {
    asm volatile("ldmatrix.sync.aligned.m8n8.x4.shared.b16 {%0,%1,%2,%3}, [%4];"
                 : "=r"(r0), "=r"(r1), "=r"(r2), "=r"(r3) : "r"(addr));
}
__device__ __forceinline__ void mma16816(float* c,
                                         unsigned a0, unsigned a1,
                                         unsigned a2, unsigned a3,
                                         unsigned b0, unsigned b1) {
    asm volatile(
        "mma.sync.aligned.m16n8k16.row.col.f32.bf16.bf16.f32 "
        "{%0,%1,%2,%3}, {%4,%5,%6,%7}, {%8,%9}, {%0,%1,%2,%3};"
        : "+f"(c[0]), "+f"(c[1]), "+f"(c[2]), "+f"(c[3])
        : "r"(a0), "r"(a1), "r"(a2), "r"(a3), "r"(b0), "r"(b1));
}

// Merge-reduce 4 values with 6 shfls; lane picks result by (bit16,bit8):
// (0,0)->p0 (1,0)->p1 (0,1)->p2 (1,1)->p3.
__device__ __forceinline__ float merge4(float p0, float p1, float p2, float p3,
                                        int lane)
{
    const bool b16 = (lane & 16) != 0;
    const bool b8  = (lane & 8)  != 0;
    float x1 = (b16 ? p1 : p0) + __shfl_xor_sync(FULLMASK, b16 ? p0 : p1, 16);
    float x2 = (b16 ? p3 : p2) + __shfl_xor_sync(FULLMASK, b16 ? p2 : p3, 16);
    float y  = (b8 ? x2 : x1)  + __shfl_xor_sync(FULLMASK, b8 ? x1 : x2, 8);
    y += __shfl_xor_sync(FULLMASK, y, 4);
    y += __shfl_xor_sync(FULLMASK, y, 2);
    y += __shfl_xor_sync(FULLMASK, y, 1);
    return y;
}

// ===========================================================================
// CHAIN v5: warp-level bf16 mma.sync (HMMA.16816). 1 sample / 128 threads.
// D(64x64) = A(64x64) @ B, A[i][k]=C[i][k], Bs[n][k]=Dm[k][n] (row.col form),
// pads zero-filled. 144B smem row stride -> conflict-free ldmatrix.
// Warp w: m-tile [16w,16w+16); 8 n-tiles; 4 k-steps.
// ===========================================================================
#define ASTRIDE 72     // bf16 elements per row (144 B)
__global__ void __launch_bounds__(128) chain_kernel(
    const int* __restrict__ nfc, const float* __restrict__ rel)
{
    __shared__ __align__(16) __nv_bfloat16 AB[2 * 64 * ASTRIDE];  // 18432 B
    __shared__ float red[4];

    const int s    = blockIdx.x;
    const int tid  = threadIdx.x;
    const int wid  = tid >> 5;
    const int lane = tid & 31;
    const int i0 = nfc[3 * s], i1 = nfc[3 * s + 1], i2 = nfc[3 * s + 2];

    // zero both tiles (covers all padding)
    {
        uint4 z = make_uint4(0, 0, 0, 0);
        uint4* z4 = (uint4*)AB;
        #pragma unroll
        for (int t = 0; t < 9; t++) z4[t * 128 + tid] = z;
    }
    __syncthreads();

    __nv_bfloat16* As = AB;
    __nv_bfloat16* Bs = AB + 64 * ASTRIDE;
    {
        const float* __restrict__ C  = rel + (long)i0 * DD;
        const float* __restrict__ Dm = rel + (long)i1 * DD;
        #pragma unroll 3
        for (int t = tid; t < DD; t += 128) {
            const int i = t / 51;
            const int k = t - i * 51;
            As[i * ASTRIDE + k] = __float2bfloat16(C[t]);
        }
        #pragma unroll 3
        for (int t = tid; t < DD; t += 128) {
            const int k = t / 51;
            const int n = t - k * 51;
            Bs[n * ASTRIDE + k] = __float2bfloat16(Dm[t]);
        }
    }
    __syncthreads();

    float acc[8][4];
    #pragma unroll
    for (int nt = 0; nt < 8; nt++)
        #pragma unroll
        for (int q = 0; q < 4; q++) acc[nt][q] = 0.f;

    // ldmatrix address patterns (bytes)
    const unsigned As_u = smem_u32(As);
    const unsigned Bs_u = smem_u32(Bs);
    // A x4: matrices (m0-7,k0-7),(m8-15,k0-7),(m0-7,k8-15),(m8-15,k8-15)
    const int a_row = 16 * wid + (lane & 7) + ((lane >> 3) & 1) * 8;
    const unsigned a_base = As_u + (unsigned)(a_row * ASTRIDE + (lane >> 4) * 8) * 2;
    // B x4 (covers n-tiles ntp*2, ntp*2+1): group=lane>>3:
    //   row = 8*(2ntp + (group>>1)) + lane&7 ; col = (group&1)*8 + kt*16
    const int b_row = (lane & 7) + ((lane >> 4)) * 8;      // (group>>1)*8
    const int b_col = ((lane >> 3) & 1) * 8;
    const unsigned b_base = Bs_u + (unsigned)(b_row * ASTRIDE + b_col) * 2;

    #pragma unroll
    for (int kt = 0; kt < 4; kt++) {
        unsigned a0, a1, a2, a3;
        ldsm_x4(a0, a1, a2, a3, a_base + kt * 32);
        #pragma unroll
        for (int ntp = 0; ntp < 4; ntp++) {
            unsigned b0, b1, b2, b3;
            ldsm_x4(b0, b1, b2, b3,
                    b_base + (unsigned)(16 * ntp * ASTRIDE) * 2 + kt * 32);
            mma16816(acc[2 * ntp],     a0, a1, a2, a3, b0, b1);
            mma16816(acc[2 * ntp + 1], a0, a1, a2, a3, b2, b3);
        }
    }
    __syncthreads();

    // stage E (fp32) into AB (10404 B <= 18432 B)
    float* Ef = (float*)AB;
    {
        const float* __restrict__ E = rel + (long)i2 * DD;
        #pragma unroll 3
        for (int t = tid; t < DD; t += 128) Ef[t] = E[t];
    }
    __syncthreads();

    // epilogue: c0:(m0,n) c1:(m0,n+1) c2:(m0+8,n) c3:(m0+8,n+1)
    float local = 0.f;
    {
        const int m0 = 16 * wid + (lane >> 2);
        const int m1 = m0 + 8;
        const int nb = 2 * (lane & 3);
        const bool v0 = (m0 < DIM), v1 = (m1 < DIM);
        #pragma unroll
        for (int nt = 0; nt < 8; nt++) {
            const int n = 8 * nt + nb;
            const bool w0 = (n < DIM), w1 = (n + 1 < DIM);
            if (v0) {
                if (w0) local += fabsf(Ef[m0 * DIM + n]     - acc[nt][0]);
                if (w1) local += fabsf(Ef[m0 * DIM + n + 1] - acc[nt][1]);
            }
            if (v1) {
                if (w0) local += fabsf(Ef[m1 * DIM + n]     - acc[nt][2]);
                if (w1) local += fabsf(Ef[m1 * DIM + n + 1] - acc[nt][3]);
            }
        }
    }
    #pragma unroll
    for (int o = 16; o; o >>= 1)
        local += __shfl_xor_sync(FULLMASK, local, o);
    if ((tid & 31) == 0) red[tid >> 5] = local;
    __syncthreads();
    if (tid == 0)
        g_part[PART_CHAIN + s] =
            (red[0] + red[1] + red[2] + red[3]) * (1.0f / (float)DD);
}

// ===========================================================================
// BMV (warp/sample) + SMALL tail blocks. (unchanged: 69 us, 57% DRAM, occ 83%)
// ===========================================================================
__global__ void __launch_bounds__(128) bmv_kernel(
    const int* __restrict__ nf1,  const int* __restrict__ nf2,
    const int* __restrict__ nf3,  const int* __restrict__ nf4,
    const int* __restrict__ top,  const int* __restrict__ nf3n,
    const int* __restrict__ radius,
    const float* __restrict__ cls, const float* __restrict__ rel)
{
    const int g   = blockIdx.x;
    const int tid = threadIdx.x;

    if (g < BMV_BLOCKS) {
        const int wl   = tid >> 5;
        const int lane = tid & 31;
        const int w    = g * 4 + wl;
        const int mode = w >> 13;
        const int s    = w & (BATCH - 1);

        const int* __restrict__ idx =
            (mode == 0) ? nf1 : (mode == 1) ? nf3 : (mode == 2) ? nf4 : nf3n;
        int ic, ir, id_;
        if (mode == 2) { ir = idx[3 * s]; ic = idx[3 * s + 1]; id_ = idx[3 * s + 2]; }
        else           { ic = idx[3 * s]; ir = idx[3 * s + 1]; id_ = idx[3 * s + 2]; }

        const float* __restrict__ rm = rel + (long)ir * DD;
        const bool hi = (lane < DIM - 32);      // lanes 0..18

        float xa[4], xb[4], na[4], nb[4];
        #pragma unroll
        for (int u = 0; u < 4; u++) {
            const float* __restrict__ row = rm + u * DIM;
            xa[u] = row[lane];
            xb[u] = hi ? row[lane + 32] : 0.f;
        }
        #pragma unroll
        for (int u = 0; u < 4; u++) {
            const float* __restrict__ row = rm + (4 + u) * DIM;
            na[u] = row[lane];
            nb[u] = hi ? row[lane + 32] : 0.f;
        }
        const float* __restrict__ cp = cls + (long)ic  * DIM;
        const float* __restrict__ dp = cls + (long)id_ * DIM;
        const float c0 = cp[lane];
        const float d0 = dp[lane];
        const float c1 = hi ? cp[lane + 32] : 0.f;
        const float d1 = hi ? dp[lane + 32] : 0.f;
        const float* __restrict__ r50 = rm + 50 * DIM;
        const float r50a = r50[lane];
        const float r50b = hi ? r50[lane + 32] : 0.f;

        const float e0 = d0 - c0;
        const float e1 = d1 - c1;

        const float scp = c0 * c0 + ((lane < 18) ? c1 * c1 : 0.f);
        const float sdp = d0 * d0 + ((lane < 18) ? d1 * d1 : 0.f);
        float scv;
        {
            const bool b16 = (lane & 16) != 0;
            float v = (b16 ? sdp : scp) +
                      __shfl_xor_sync(FULLMASK, b16 ? scp : sdp, 16);
            v += __shfl_xor_sync(FULLMASK, v, 8);
            v += __shfl_xor_sync(FULLMASK, v, 4);
            v += __shfl_xor_sync(FULLMASK, v, 2);
            v += __shfl_xor_sync(FULLMASK, v, 1);
            scv = v;
        }
        const float sc_tot = __shfl_sync(FULLMASK, scv, 0);
        const float sd_tot = __shfl_sync(FULLMASK, scv, 16);
        const float c_last = __shfl_sync(FULLMASK, c1, 18);
        const float d_last = __shfl_sync(FULLMASK, d1, 18);

        float vsq = 0.f;
        #pragma unroll
        for (int gr = 0; gr < 13; gr++) {
            float p[4];
            float* A = ((gr & 1) == 0) ? xa : na;
            float* B = ((gr & 1) == 0) ? xb : nb;
            #pragma unroll
            for (int u = 0; u < 4; u++) {
                const bool valid = (4 * gr + u) < 50;
                p[u] = valid ? (A[u] * e0 + B[u] * e1) : 0.f;
            }
            if (gr + 2 < 13) {
                #pragma unroll
                for (int u = 0; u < 4; u++) {
                    const int r = (gr + 2) * 4 + u;
                    if (r < 50) {
                        const float* __restrict__ row = rm + r * DIM;
                        A[u] = row[lane];
                        B[u] = hi ? row[lane + 32] : 0.f;
                    }
                }
            }
            const float y = merge4(p[0], p[1], p[2], p[3], lane);
            vsq = fmaf(y, y, vsq);
        }
        #pragma unroll
        for (int o = 16; o; o >>= 1)
            vsq += __shfl_xor_sync(FULLMASK, vsq, o);
        const float euc = sqrtf(vsq * 0.125f);   // sum vsq = 8 * euc2

        float core;
        if (mode == 0) {
            const float pcp = r50a * c0 + r50b * c1;
            const float pdp = r50a * d0 + r50b * d1;
            const float yv = merge4(pcp, pdp, 0.f, 0.f, lane);
            const float pc = __shfl_sync(FULLMASK, yv, 0);
            const float pd = __shfl_sync(FULLMASK, yv, 16);
            core = fmaxf(euc + fmaxf(pc, 0.f) - fmaxf(pd, 0.f), 0.f);
        } else {
            const float rc = fmaxf(c_last, 0.f);
            const float rd = fmaxf(d_last, 0.f);
            if (mode == 1)      core = fmaxf(euc + rc - rd, 0.f);
            else if (mode == 2) core = fmaxf(euc - rc - rd, 0.f);
            else                core = rc + rd - euc;           // nf3_neg
        }
        if (lane == 0)
            g_part[PART_BMV + w] = core + fabsf(sqrtf(sc_tot) - 1.0f)
                                        + fabsf(sqrtf(sd_tot) - 1.0f);

    } else {
        // ------------------------- SMALL (nf2 + top - radius) -------------
        __shared__ float red[4];
        const int s = (g - BMV_BLOCKS) * 128 + tid;
        const float* __restrict__ c = cls + (long)nf2[3 * s]     * DIM;
        const float* __restrict__ d = cls + (long)nf2[3 * s + 1] * DIM;
        const float* __restrict__ e = cls + (long)nf2[3 * s + 2] * DIM;

        float s12 = 0.f, s13 = 0.f, s23 = 0.f, n1 = 0.f, n2 = 0.f, n3 = 0.f;
        #pragma unroll 5
        for (int k = 0; k < DIM - 1; k++) {
            const float x1 = c[k], x2 = d[k], x3 = e[k];
            const float d12 = x2 - x1, d13 = x3 - x1, d23 = x3 - x2;
            s12 = fmaf(d12, d12, s12);
            s13 = fmaf(d13, d13, s13);
            s23 = fmaf(d23, d23, s23);
            n1  = fmaf(x1, x1, n1);
            n2  = fmaf(x2, x2, n2);
            n3  = fmaf(x3, x3, n3);
        }
        const float rc = fmaxf(c[DIM - 1], 0.f);
        const float rd = fmaxf(d[DIM - 1], 0.f);
        const float re = fmaxf(e[DIM - 1], 0.f);
        float v = fmaxf(sqrtf(s12) - (rc + rd), 0.f)
                + fmaxf(sqrtf(s13) - rc, 0.f)
                + fmaxf(sqrtf(s23) - rd, 0.f)
                + fmaxf(fminf(rc, rd) - re, 0.f)
                + fabsf(sqrtf(n1) - 1.f)
                + fabsf(sqrtf(n2) - 1.f)
                + fabsf(sqrtf(n3) - 1.f);

        v += fabsf(fmaxf(cls[(long)top[s] * DIM + (DIM - 1)], 0.f) - 5.0f);
        v -= fminf(0.f, cls[(long)radius[s] * DIM + (DIM - 1)]);

        #pragma unroll
        for (int o = 16; o; o >>= 1)
            v += __shfl_xor_sync(FULLMASK, v, o);
        if ((tid & 31) == 0) red[tid >> 5] = v;
        __syncthreads();
        if (tid == 0)
            g_part[PART_SMALL + (g - BMV_BLOCKS)] =
                (red[0] + red[1]) + (red[2] + red[3]);
    }
}

// ---------------------------------------------------------------------------
__global__ void __launch_bounds__(1024) finish_kernel(float* __restrict__ out)
{
    float t = 0.f;
    for (int i = threadIdx.x; i < PART_TOTAL; i += 1024) t += g_part[i];
    #pragma unroll
    for (int o = 16; o; o >>= 1)
        t += __shfl_xor_sync(FULLMASK, t, o);
    __shared__ float ws[32];
    if ((threadIdx.x & 31) == 0) ws[threadIdx.x >> 5] = t;
    __syncthreads();
    if (threadIdx.x < 32) {
        float v = ws[threadIdx.x];
        #pragma unroll
        for (int o = 16; o; o >>= 1)
            v += __shfl_xor_sync(FULLMASK, v, o);
        if (threadIdx.x == 0) out[0] = v * (1.0f / (float)BATCH);
    }
}

// ---------------------------------------------------------------------------
// Side stream + events for chain||bmv overlap (host driver resources only).
// ---------------------------------------------------------------------------
static cudaStream_t g_s2 = 0;
static cudaEvent_t  g_evA = 0, g_evB = 0;
namespace {
struct StreamInit {
    StreamInit() {
        if (cudaStreamCreateWithFlags(&g_s2, cudaStreamNonBlocking) != cudaSuccess) {
            g_s2 = 0;
            return;
        }
        if (cudaEventCreateWithFlags(&g_evA, cudaEventDisableTiming) != cudaSuccess ||
            cudaEventCreateWithFlags(&g_evB, cudaEventDisableTiming) != cudaSuccess) {
            g_s2 = 0;
        }
    }
};
static StreamInit g_streamInit;
}

// ---------------------------------------------------------------------------
// Inputs: 0 nf1 1 nf2 2 nf3 3 nf4 4 top 5 nf3_neg 6 nf_inclusion(unused)
//         7 nf_chain 8 radius 9 cls_emb 10 rel_emb
// Kernel launch order chain,bmv,finish -> profiled launch (#4) = chain.
// ---------------------------------------------------------------------------
extern "C" void kernel_launch(void* const* d_in, const int* in_sizes, int n_in,
                              void* d_out, int out_size)
{
    const int*   nf1    = (const int*)d_in[0];
    const int*   nf2    = (const int*)d_in[1];
    const int*   nf3    = (const int*)d_in[2];
    const int*   nf4    = (const int*)d_in[3];
    const int*   top    = (const int*)d_in[4];
    const int*   nf3n   = (const int*)d_in[5];
    const int*   nfc    = (const int*)d_in[7];
    const int*   radius = (const int*)d_in[8];
    const float* cls    = (const float*)d_in[9];
    const float* rel    = (const float*)d_in[10];
    float*       out    = (float*)d_out;

    if (g_s2) {
        cudaEventRecord(g_evA, 0);
        cudaStreamWaitEvent(g_s2, g_evA, 0);
        chain_kernel<<<CHAIN_BLOCKS, 128>>>(nfc, rel);
        bmv_kernel<<<BMVK_BLOCKS, 128, 0, g_s2>>>(nf1, nf2, nf3, nf4, top,
                                                  nf3n, radius, cls, rel);
        cudaEventRecord(g_evB, g_s2);
        cudaStreamWaitEvent(0, g_evB, 0);
        finish_kernel<<<1, 1024>>>(out);
    } else {
        chain_kernel<<<CHAIN_BLOCKS, 128>>>(nfc, rel);
        bmv_kernel<<<BMVK_BLOCKS, 128>>>(nf1, nf2, nf3, nf4, top, nf3n,
                                         radius, cls, rel);
        finish_kernel<<<1, 1024>>>(out);
    }
}